// round 2
// baseline (speedup 1.0000x reference)
#include <cuda_runtime.h>
#include <math.h>

#define N_NODES 20000
#define K_NB    32
#define D_DIM   128
#define PAD     132   // padded row stride (floats) for lv/nv/part tiles

// ---------------- scratch (device globals: allocation-free) ----------------
__device__ float g_tsf[(size_t)N_NODES * D_DIM];   // self_feats @ self_weights
__device__ float g_tself[N_NODES];                 // self_vecs . gate_self_w

__device__ __forceinline__ float sigmoidf_fast(float x) {
    // 1 / (1 + e^-x)  -> FMUL + MUFU.EX2 + MUFU.RCP
    float t = __expf(-x);
    return __fdividef(1.0f, 1.0f + t);
}

// ---------------- kernel 1: tself[n] = dot(self_vecs[n], gate_self_w) ------
__global__ void k_tself(const float* __restrict__ self_vecs,
                        const float* __restrict__ gws) {
    int gtid = blockIdx.x * blockDim.x + threadIdx.x;
    int node = gtid >> 5;
    int lane = gtid & 31;
    if (node >= N_NODES) return;
    const float4* sv = (const float4*)(self_vecs + (size_t)node * D_DIM);
    const float4* gw = (const float4*)gws;
    float4 a = sv[lane];
    float4 b = __ldg(&gw[lane]);
    float s = a.x * b.x + a.y * b.y + a.z * b.z + a.w * b.w;
    #pragma unroll
    for (int o = 16; o > 0; o >>= 1) s += __shfl_down_sync(0xffffffffu, s, o);
    if (lane == 0) g_tself[node] = s;
}

// ---------------- kernel 2: tsf = self_feats @ self_weights ----------------
#define TSF_NODES 16
__global__ void k_tsf(const float* __restrict__ self_feats,
                      const float* __restrict__ Ws) {
    extern __shared__ float sm[];
    float* Wsh = sm;                       // 128*128
    float* sfs = sm + D_DIM * D_DIM;       // 16*128
    int t = threadIdx.x;

    for (int i = t; i < (D_DIM * D_DIM) / 4; i += 256)
        ((float4*)Wsh)[i] = ((const float4*)Ws)[i];

    int nbase = blockIdx.x * TSF_NODES;
    const float4* gsf = (const float4*)(self_feats + (size_t)nbase * D_DIM);
    for (int i = t; i < (TSF_NODES * D_DIM) / 4; i += 256)
        ((float4*)sfs)[i] = gsf[i];
    __syncthreads();

    int e = t & 127;
    int g = t >> 7;                        // 2 groups x 8 nodes
    float acc[8];
    #pragma unroll
    for (int m = 0; m < 8; m++) acc[m] = 0.0f;

    #pragma unroll 4
    for (int d = 0; d < D_DIM; d++) {
        float w = Wsh[d * D_DIM + e];
        #pragma unroll
        for (int m = 0; m < 8; m++)
            acc[m] = fmaf(w, sfs[(g * 8 + m) * D_DIM + d], acc[m]);
    }
    #pragma unroll
    for (int m = 0; m < 8; m++)
        g_tsf[(size_t)(nbase + g * 8 + m) * D_DIM + e] = acc[m];
}

// ---------------- kernel 3: main fused aggregator --------------------------
// One block = 256 threads = 8 warps; each iteration processes 2 nodes
// (64 combined k-rows). Warp w owns rows [w*8, w*8+8); lane owns cols e4=lane*4.
__global__ void __launch_bounds__(256, 1)
k_main(const float* __restrict__ neigh,
       const float* __restrict__ link,
       const float* __restrict__ probs,
       const float* __restrict__ gwn,
       const float* __restrict__ gwl,
       const float* __restrict__ Wl,
       float* __restrict__ out) {
    extern __shared__ float sm[];
    float* Wlsh = sm;                        // 16384
    float* lvs  = Wlsh + D_DIM * D_DIM;      // 64*132 = 8448
    float* nvs  = lvs + 64 * PAD;            // 8448
    float* part = nvs + 64 * PAD;            // 8*132 = 1056
    float* csh  = part + 8 * PAD;            // 64
    float* gwns = csh + 64;                  // 128
    float* gwls = gwns + D_DIM;              // 128

    int t = threadIdx.x;
    int warp = t >> 5, lane = t & 31;
    int e4 = lane * 4;
    int kbase = warp * 8;

    for (int i = t; i < (D_DIM * D_DIM) / 4; i += 256)
        ((float4*)Wlsh)[i] = ((const float4*)Wl)[i];
    if (t < D_DIM) { gwns[t] = gwn[t]; gwls[t] = gwl[t]; }

    for (int p = blockIdx.x; p < N_NODES / 2; p += gridDim.x) {
        int nA = p * 2, nB = p * 2 + 1;
        __syncthreads();   // tiles from prev iter fully consumed; Wl ready (iter 0)

        // ---- load lv / nv tiles (64 rows x 128), one row per warp per step
        for (int row = warp; row < 64; row += 8) {
            int node = (row < 32) ? nA : nB;
            int k = row & 31;
            size_t base = ((size_t)node * K_NB + k) * D_DIM;
            float4 v = ((const float4*)(link + base))[lane];
            float4 u = ((const float4*)(neigh + base))[lane];
            float* dl = lvs + row * PAD + e4;
            dl[0] = v.x; dl[1] = v.y; dl[2] = v.z; dl[3] = v.w;
            float* dn = nvs + row * PAD + e4;
            dn[0] = u.x; dn[1] = u.y; dn[2] = u.z; dn[3] = u.w;
        }
        __syncthreads();

        // ---- gate coefficients c[kk] = sigmoid(tself + nv.gwn + lv.gwl)/(p*K)
        {
            int kk = t >> 2, sub = t & 3;          // 64 k-rows, 4 threads each
            const float* lrow = lvs + kk * PAD;
            const float* nrow = nvs + kk * PAD;
            float s = 0.0f;
            int d0 = sub * 32;
            #pragma unroll 8
            for (int i = 0; i < 32; i++) {
                int d = d0 + i;
                s = fmaf(lrow[d], gwls[d], s);
                s = fmaf(nrow[d], gwns[d], s);
            }
            s += __shfl_down_sync(0xffffffffu, s, 1);
            s += __shfl_down_sync(0xffffffffu, s, 2);
            if (sub == 0) {
                int node = (kk < 32) ? nA : nB;
                int k = kk & 31;
                float g = sigmoidf_fast(g_tself[node] + s);
                csh[kk] = __fdividef(g, probs[(size_t)node * K_NB + k]) *
                          (1.0f / (float)K_NB);
            }
        }
        __syncthreads();

        // ---- GEMM: L[kk][e] = sum_d lv[kk][d] * Wl[d][e]
        float acc[8][4];
        #pragma unroll
        for (int r = 0; r < 8; r++)
            acc[r][0] = acc[r][1] = acc[r][2] = acc[r][3] = 0.0f;

        #pragma unroll 4
        for (int d = 0; d < D_DIM; d++) {
            float4 w = *(const float4*)&Wlsh[d * D_DIM + e4];
            #pragma unroll
            for (int r = 0; r < 8; r++) {
                float lv = lvs[(kbase + r) * PAD + d];
                acc[r][0] = fmaf(lv, w.x, acc[r][0]);
                acc[r][1] = fmaf(lv, w.y, acc[r][1]);
                acc[r][2] = fmaf(lv, w.z, acc[r][2]);
                acc[r][3] = fmaf(lv, w.w, acc[r][3]);
            }
        }

        // ---- epilogue: ps[e] = sum_r nv * sigmoid(L) * c
        float ps0 = 0.f, ps1 = 0.f, ps2 = 0.f, ps3 = 0.f;
        #pragma unroll
        for (int r = 0; r < 8; r++) {
            float c = csh[kbase + r];
            float4 nv4 = *(const float4*)&nvs[(kbase + r) * PAD + e4];
            ps0 = fmaf(nv4.x * sigmoidf_fast(acc[r][0]), c, ps0);
            ps1 = fmaf(nv4.y * sigmoidf_fast(acc[r][1]), c, ps1);
            ps2 = fmaf(nv4.z * sigmoidf_fast(acc[r][2]), c, ps2);
            ps3 = fmaf(nv4.w * sigmoidf_fast(acc[r][3]), c, ps3);
        }
        float4 pv = make_float4(ps0, ps1, ps2, ps3);
        *(float4*)&part[warp * PAD + e4] = pv;
        __syncthreads();

        // ---- cross-warp k reduction + tsf scale + relu + store
        {
            int e = t & 127, nd = t >> 7;
            float s = 0.0f;
            #pragma unroll
            for (int w = 0; w < 4; w++) s += part[(nd * 4 + w) * PAD + e];
            int node = nd ? nB : nA;
            float r = g_tsf[(size_t)node * D_DIM + e] * s;
            out[(size_t)node * D_DIM + e] = fmaxf(r, 0.0f);
        }
    }
}

// ---------------- launch ----------------------------------------------------
extern "C" void kernel_launch(void* const* d_in, const int* in_sizes, int n_in,
                              void* d_out, int out_size) {
    const float* self_feats = (const float*)d_in[0];
    const float* self_vecs  = (const float*)d_in[1];
    const float* neigh      = (const float*)d_in[2];
    const float* link       = (const float*)d_in[3];
    const float* probs      = (const float*)d_in[4];
    const float* gws        = (const float*)d_in[5];
    const float* gwn        = (const float*)d_in[6];
    const float* gwl        = (const float*)d_in[7];
    const float* Ws         = (const float*)d_in[8];
    const float* Wl         = (const float*)d_in[9];
    float* out = (float*)d_out;

    const int smem_tsf  = (D_DIM * D_DIM + TSF_NODES * D_DIM) * sizeof(float);   // 72 KB
    const int smem_main = (D_DIM * D_DIM + 64 * PAD + 64 * PAD + 8 * PAD + 64 +
                           2 * D_DIM) * sizeof(float);                           // ~135 KB

    cudaFuncSetAttribute(k_tsf,  cudaFuncAttributeMaxDynamicSharedMemorySize, smem_tsf);
    cudaFuncSetAttribute(k_main, cudaFuncAttributeMaxDynamicSharedMemorySize, smem_main);

    k_tself<<<(N_NODES * 32 + 255) / 256, 256>>>(self_vecs, gws);
    k_tsf<<<N_NODES / TSF_NODES, 256, smem_tsf>>>(self_feats, Ws);
    k_main<<<148, 256, smem_main>>>(neigh, link, probs, gwn, gwl, Wl, out);
}

// round 3
// speedup vs baseline: 1.7222x; 1.7222x over previous
#include <cuda_runtime.h>
#include <math.h>

#define N_NODES 20000
#define K_NB    32
#define D_DIM   128
#define PAD     132   // padded row stride (floats): bank-conflict-free fragments

// ---------------- scratch (device globals: allocation-free) ----------------
__device__ float g_tsf[(size_t)N_NODES * D_DIM];   // self_feats @ self_weights
__device__ float g_tself[N_NODES];                 // self_vecs . gate_self_w

__device__ __forceinline__ float sigmoid_tanh(float x) {
    // sigmoid(x) = 0.5*tanh(0.5x)+0.5   (single MUFU.TANH)
    float t;
    asm("tanh.approx.f32 %0, %1;" : "=f"(t) : "f"(0.5f * x));
    return fmaf(0.5f, t, 0.5f);
}

__device__ __forceinline__ unsigned f2tf32(float x) {
    unsigned u;
    asm("cvt.rna.tf32.f32 %0, %1;" : "=r"(u) : "f"(x));
    return u;
}

__device__ __forceinline__ void cp16(void* dst, const void* src) {
    unsigned sa = (unsigned)__cvta_generic_to_shared(dst);
    asm volatile("cp.async.cg.shared.global [%0], [%1], 16;\n" :: "r"(sa), "l"(src));
}
__device__ __forceinline__ void cp_commit() {
    asm volatile("cp.async.commit_group;\n");
}
__device__ __forceinline__ void cp_wait0() {
    asm volatile("cp.async.wait_group 0;\n");
}

__device__ __forceinline__ void mma_tf32(float& c0, float& c1, float& c2, float& c3,
                                         unsigned a0, unsigned a1, unsigned a2, unsigned a3,
                                         unsigned b0, unsigned b1) {
    asm volatile(
        "mma.sync.aligned.m16n8k8.row.col.f32.tf32.tf32.f32 "
        "{%0,%1,%2,%3}, {%4,%5,%6,%7}, {%8,%9}, {%0,%1,%2,%3};\n"
        : "+f"(c0), "+f"(c1), "+f"(c2), "+f"(c3)
        : "r"(a0), "r"(a1), "r"(a2), "r"(a3), "r"(b0), "r"(b1));
}

// ---------------- kernel 1: tself[n] = dot(self_vecs[n], gate_self_w) ------
__global__ void k_tself(const float* __restrict__ self_vecs,
                        const float* __restrict__ gws) {
    int gtid = blockIdx.x * blockDim.x + threadIdx.x;
    int node = gtid >> 5;
    int lane = gtid & 31;
    if (node >= N_NODES) return;
    const float4* sv = (const float4*)(self_vecs + (size_t)node * D_DIM);
    const float4* gw = (const float4*)gws;
    float4 a = sv[lane];
    float4 b = __ldg(&gw[lane]);
    float s = a.x * b.x + a.y * b.y + a.z * b.z + a.w * b.w;
    #pragma unroll
    for (int o = 16; o > 0; o >>= 1) s += __shfl_down_sync(0xffffffffu, s, o);
    if (lane == 0) g_tself[node] = s;
}

// ---------------- kernel 2: tsf = self_feats @ self_weights ----------------
#define TSF_NODES 16
__global__ void k_tsf(const float* __restrict__ self_feats,
                      const float* __restrict__ Ws) {
    extern __shared__ float sm[];
    float* Wsh = sm;                       // 128*128
    float* sfs = sm + D_DIM * D_DIM;       // 16*128
    int t = threadIdx.x;

    for (int i = t; i < (D_DIM * D_DIM) / 4; i += 256)
        ((float4*)Wsh)[i] = ((const float4*)Ws)[i];

    int nbase = blockIdx.x * TSF_NODES;
    const float4* gsf = (const float4*)(self_feats + (size_t)nbase * D_DIM);
    for (int i = t; i < (TSF_NODES * D_DIM) / 4; i += 256)
        ((float4*)sfs)[i] = gsf[i];
    __syncthreads();

    int e = t & 127;
    int g = t >> 7;                        // 2 groups x 8 nodes
    float acc[8];
    #pragma unroll
    for (int m = 0; m < 8; m++) acc[m] = 0.0f;

    #pragma unroll 4
    for (int d = 0; d < D_DIM; d++) {
        float w = Wsh[d * D_DIM + e];
        #pragma unroll
        for (int m = 0; m < 8; m++)
            acc[m] = fmaf(w, sfs[(g * 8 + m) * D_DIM + d], acc[m]);
    }
    #pragma unroll
    for (int m = 0; m < 8; m++)
        g_tsf[(size_t)(nbase + g * 8 + m) * D_DIM + e] = acc[m];
}

// ---------------- kernel 3: main fused aggregator (tensor-core GEMM) -------
// 256 threads = 8 warps, warp grid 4(M) x 2(N). Per iteration: 2 nodes =
// 64 k-rows (M) x 128 cols (N), K=128 (d). tf32 mma.sync m16n8k8.
// lv/nv tiles double-buffered via cp.async.
__global__ void __launch_bounds__(256, 1)
k_main(const float* __restrict__ neigh,
       const float* __restrict__ link,
       const float* __restrict__ probs,
       const float* __restrict__ gwn,
       const float* __restrict__ gwl,
       const float* __restrict__ Wl,
       float* __restrict__ out) {
    extern __shared__ float sm[];
    float* WT   = sm;                           // 128*132  (WT[e][d] = tf32(Wl[d][e]))
    float* lvb0 = WT + D_DIM * PAD;             // 64*132
    float* lvb1 = lvb0 + 64 * PAD;
    float* nvb0 = lvb1 + 64 * PAD;
    float* nvb1 = nvb0 + 64 * PAD;
    float* csh  = nvb1 + 64 * PAD;              // 64
    float* part = csh + 64;                     // 8 * 68
    float* gwns = part + 8 * 68;                // 128
    float* gwls = gwns + D_DIM;                 // 128

    int t = threadIdx.x;
    int warp = t >> 5, lane = t & 31;
    int wm = warp >> 1, wn = warp & 1;
    int lp = lane >> 2;          // 0..7
    int lq = lane & 3;           // 0..3

    // ---- setup: WT (transposed + tf32-rounded), gate weight vectors
    for (int i = t; i < D_DIM * D_DIM; i += 256) {
        int d = i >> 7, e = i & 127;
        ((unsigned*)WT)[e * PAD + d] = f2tf32(Wl[i]);
    }
    if (t < D_DIM) { gwns[t] = gwn[t]; gwls[t] = gwl[t]; }

    float* lvbuf[2] = {lvb0, lvb1};
    float* nvbuf[2] = {nvb0, nvb1};

    // prologue: load first tile into buffer 0
    {
        int p0 = blockIdx.x;
        if (p0 < N_NODES / 2) {
            #pragma unroll
            for (int j = 0; j < 8; j++) {
                int idx = t + j * 256;           // 0..2047
                int row = idx >> 5, c4 = idx & 31;
                size_t gb = (((size_t)p0 * 64 + row) << 7) + c4 * 4;
                cp16(lvb0 + row * PAD + c4 * 4, link + gb);
                cp16(nvb0 + row * PAD + c4 * 4, neigh + gb);
            }
        }
        cp_commit();
    }

    int buf = 0;
    for (int p = blockIdx.x; p < N_NODES / 2; p += gridDim.x) {
        cp_wait0();
        __syncthreads();                          // tile ready; prev part/csh consumed

        // ---- kick next tile into other buffer
        int pn = p + gridDim.x;
        if (pn < N_NODES / 2) {
            float* ld = lvbuf[buf ^ 1];
            float* nd_ = nvbuf[buf ^ 1];
            #pragma unroll
            for (int j = 0; j < 8; j++) {
                int idx = t + j * 256;
                int row = idx >> 5, c4 = idx & 31;
                size_t gb = (((size_t)pn * 64 + row) << 7) + c4 * 4;
                cp16(ld + row * PAD + c4 * 4, link + gb);
                cp16(nd_ + row * PAD + c4 * 4, neigh + gb);
            }
        }
        cp_commit();

        const float* lvs = lvbuf[buf];
        const float* nvs = nvbuf[buf];

        // ---- gate coefficients c[kk] = sigmoid(tself + nv.gwn + lv.gwl)/(prob*K)
        {
            int kk = t >> 2, sub = t & 3;
            const float* lrow = lvs + kk * PAD + sub * 32;
            const float* nrow = nvs + kk * PAD + sub * 32;
            const float* gl = gwls + sub * 32;
            const float* gn = gwns + sub * 32;
            float s = 0.0f;
            #pragma unroll 8
            for (int i = 0; i < 32; i++) {
                s = fmaf(lrow[i], gl[i], s);
                s = fmaf(nrow[i], gn[i], s);
            }
            s += __shfl_down_sync(0xffffffffu, s, 1);
            s += __shfl_down_sync(0xffffffffu, s, 2);
            if (sub == 0) {
                int node = p * 2 + (kk >> 5);
                float g = sigmoid_tanh(g_tself[node] + s);
                csh[kk] = __fdividef(g, probs[(size_t)p * 64 + kk]) *
                          (1.0f / (float)K_NB);
            }
        }
        __syncthreads();                          // csh visible

        // ---- tensor-core GEMM: L[64 x 128] = lv[64 x 128] @ Wl[128 x 128]
        float acc[8][4];
        #pragma unroll
        for (int ns = 0; ns < 8; ns++)
            acc[ns][0] = acc[ns][1] = acc[ns][2] = acc[ns][3] = 0.0f;

        int r0 = wm * 16 + lp;                    // A rows r0, r0+8
        const float* arow0 = lvs + r0 * PAD;
        const float* arow1 = lvs + (r0 + 8) * PAD;
        const unsigned* wtb = (const unsigned*)WT + (wn * 64 + lp) * PAD + lq;

        #pragma unroll 4
        for (int ks = 0; ks < 16; ks++) {
            int d0 = ks * 8 + lq;
            unsigned a0 = f2tf32(arow0[d0]);
            unsigned a1 = f2tf32(arow1[d0]);
            unsigned a2 = f2tf32(arow0[d0 + 4]);
            unsigned a3 = f2tf32(arow1[d0 + 4]);
            const unsigned* wb = wtb + ks * 8;
            #pragma unroll
            for (int ns = 0; ns < 8; ns++) {
                unsigned b0 = wb[ns * 8 * PAD];
                unsigned b1 = wb[ns * 8 * PAD + 4];
                mma_tf32(acc[ns][0], acc[ns][1], acc[ns][2], acc[ns][3],
                         a0, a1, a2, a3, b0, b1);
            }
        }

        // ---- epilogue: per-column partial sums over this warp's 16 rows
        float cc0 = csh[r0];
        float cc1 = csh[r0 + 8];
        float ps[16];
        int e0 = wn * 64 + lq * 2;
        #pragma unroll
        for (int ns = 0; ns < 8; ns++) {
            const float* n0 = nvs + r0 * PAD + e0 + ns * 8;
            const float* n1 = nvs + (r0 + 8) * PAD + e0 + ns * 8;
            float2 nv0 = *(const float2*)n0;
            float2 nv1 = *(const float2*)n1;
            ps[ns * 2 + 0] = sigmoid_tanh(acc[ns][0]) * nv0.x * cc0 +
                             sigmoid_tanh(acc[ns][2]) * nv1.x * cc1;
            ps[ns * 2 + 1] = sigmoid_tanh(acc[ns][1]) * nv0.y * cc0 +
                             sigmoid_tanh(acc[ns][3]) * nv1.y * cc1;
        }
        // reduce across the 8 lanes sharing the same lq (rows within warp)
        #pragma unroll
        for (int o = 4; o <= 16; o <<= 1) {
            #pragma unroll
            for (int i = 0; i < 16; i++)
                ps[i] += __shfl_xor_sync(0xffffffffu, ps[i], o);
        }
        if (lane < 4) {
            float* pw = part + warp * 68;
            #pragma unroll
            for (int ns = 0; ns < 8; ns++)
                *(float2*)&pw[ns * 8 + lane * 2] =
                    make_float2(ps[ns * 2], ps[ns * 2 + 1]);
        }
        __syncthreads();                          // part visible

        // ---- cross-warp (M) reduction + tsf scale + relu + store
        {
            int e = t & 127, nd2 = t >> 7;
            int wnE = e >> 6, c = e & 63;
            float s = part[((nd2 * 2 + 0) * 2 + wnE) * 68 + c] +
                      part[((nd2 * 2 + 1) * 2 + wnE) * 68 + c];
            int node = p * 2 + nd2;
            float r = g_tsf[(size_t)node * D_DIM + e] * s;
            out[(size_t)node * D_DIM + e] = fmaxf(r, 0.0f);
        }

        buf ^= 1;
    }
}

// ---------------- launch ----------------------------------------------------
extern "C" void kernel_launch(void* const* d_in, const int* in_sizes, int n_in,
                              void* d_out, int out_size) {
    const float* self_feats = (const float*)d_in[0];
    const float* self_vecs  = (const float*)d_in[1];
    const float* neigh      = (const float*)d_in[2];
    const float* link       = (const float*)d_in[3];
    const float* probs      = (const float*)d_in[4];
    const float* gws        = (const float*)d_in[5];
    const float* gwn        = (const float*)d_in[6];
    const float* gwl        = (const float*)d_in[7];
    const float* Ws         = (const float*)d_in[8];
    const float* Wl         = (const float*)d_in[9];
    float* out = (float*)d_out;

    const int smem_tsf  = (D_DIM * D_DIM + TSF_NODES * D_DIM) * sizeof(float); // 72 KB
    const int smem_main = (D_DIM * PAD + 4 * 64 * PAD + 64 + 8 * 68 +
                           2 * D_DIM) * sizeof(float);                         // ~206 KB

    cudaFuncSetAttribute(k_tsf,  cudaFuncAttributeMaxDynamicSharedMemorySize, smem_tsf);
    cudaFuncSetAttribute(k_main, cudaFuncAttributeMaxDynamicSharedMemorySize, smem_main);

    k_tself<<<(N_NODES * 32 + 255) / 256, 256>>>(self_vecs, gws);
    k_tsf<<<N_NODES / TSF_NODES, 256, smem_tsf>>>(self_feats, Ws);
    k_main<<<148, 256, smem_main>>>(neigh, link, probs, gwn, gwl, Wl, out);
}

// round 4
// speedup vs baseline: 2.1320x; 1.2380x over previous
#include <cuda_runtime.h>
#include <math.h>

#define N_NODES 20000
#define K_NB    32
#define D_DIM   128
#define PAD     132   // padded row stride (floats)

// ---------------- scratch (device globals: allocation-free) ----------------
__device__ float g_tsf[(size_t)N_NODES * D_DIM];   // self_feats @ self_weights
__device__ float g_tself[N_NODES];                 // self_vecs . gate_self_w

__device__ __forceinline__ float sigmoid_tanh(float x) {
    float t;
    asm("tanh.approx.f32 %0, %1;" : "=f"(t) : "f"(0.5f * x));
    return fmaf(0.5f, t, 0.5f);
}

__device__ __forceinline__ unsigned f2tf32(float x) {
    unsigned u;
    asm("cvt.rna.tf32.f32 %0, %1;" : "=r"(u) : "f"(x));
    return u;
}

__device__ __forceinline__ void cp16(void* dst, const void* src) {
    unsigned sa = (unsigned)__cvta_generic_to_shared(dst);
    asm volatile("cp.async.cg.shared.global [%0], [%1], 16;\n" :: "r"(sa), "l"(src));
}
__device__ __forceinline__ void cp_commit() {
    asm volatile("cp.async.commit_group;\n");
}
__device__ __forceinline__ void cp_wait0() {
    asm volatile("cp.async.wait_group 0;\n");
}

__device__ __forceinline__ void mma_tf32(float& c0, float& c1, float& c2, float& c3,
                                         unsigned a0, unsigned a1, unsigned a2, unsigned a3,
                                         unsigned b0, unsigned b1) {
    asm volatile(
        "mma.sync.aligned.m16n8k8.row.col.f32.tf32.tf32.f32 "
        "{%0,%1,%2,%3}, {%4,%5,%6,%7}, {%8,%9}, {%0,%1,%2,%3};\n"
        : "+f"(c0), "+f"(c1), "+f"(c2), "+f"(c3)
        : "r"(a0), "r"(a1), "r"(a2), "r"(a3), "r"(b0), "r"(b1));
}

// ---------------- kernel 1: tself[n] = dot(self_vecs[n], gate_self_w) ------
__global__ void k_tself(const float* __restrict__ self_vecs,
                        const float* __restrict__ gws) {
    int gtid = blockIdx.x * blockDim.x + threadIdx.x;
    int node = gtid >> 5;
    int lane = gtid & 31;
    if (node >= N_NODES) return;
    const float4* sv = (const float4*)(self_vecs + (size_t)node * D_DIM);
    const float4* gw = (const float4*)gws;
    float4 a = sv[lane];
    float4 b = __ldg(&gw[lane]);
    float s = a.x * b.x + a.y * b.y + a.z * b.z + a.w * b.w;
    #pragma unroll
    for (int o = 16; o > 0; o >>= 1) s += __shfl_down_sync(0xffffffffu, s, o);
    if (lane == 0) g_tself[node] = s;
}

// ---------------- kernel 2: tsf = self_feats @ self_weights ----------------
#define TSF_NODES 16
__global__ void k_tsf(const float* __restrict__ self_feats,
                      const float* __restrict__ Ws) {
    extern __shared__ float sm[];
    float* Wsh = sm;                       // 128*128
    float* sfs = sm + D_DIM * D_DIM;       // 16*128
    int t = threadIdx.x;

    for (int i = t; i < (D_DIM * D_DIM) / 4; i += 256)
        ((float4*)Wsh)[i] = ((const float4*)Ws)[i];

    int nbase = blockIdx.x * TSF_NODES;
    const float4* gsf = (const float4*)(self_feats + (size_t)nbase * D_DIM);
    for (int i = t; i < (TSF_NODES * D_DIM) / 4; i += 256)
        ((float4*)sfs)[i] = gsf[i];
    __syncthreads();

    int e = t & 127;
    int g = t >> 7;
    float acc[8];
    #pragma unroll
    for (int m = 0; m < 8; m++) acc[m] = 0.0f;

    #pragma unroll 4
    for (int d = 0; d < D_DIM; d++) {
        float w = Wsh[d * D_DIM + e];
        #pragma unroll
        for (int m = 0; m < 8; m++)
            acc[m] = fmaf(w, sfs[(g * 8 + m) * D_DIM + d], acc[m]);
    }
    #pragma unroll
    for (int m = 0; m < 8; m++)
        g_tsf[(size_t)(nbase + g * 8 + m) * D_DIM + e] = acc[m];
}

// ---------------- kernel 3: main fused aggregator --------------------------
// 256 threads = 8 warps, warp grid 2(M) x 4(N). Per iteration: 2 nodes =
// 64 rows(M) x 128 cols(N), K=128. Warp (wm, wn) owns node p*2+wm,
// cols [wn*32, wn*32+32). B fragments live in registers for the whole loop.
__global__ void __launch_bounds__(256, 1)
k_main(const float* __restrict__ neigh,
       const float* __restrict__ link,
       const float* __restrict__ probs,
       const float* __restrict__ gwn,
       const float* __restrict__ gwl,
       const float* __restrict__ Wl,
       float* __restrict__ out) {
    extern __shared__ float sm[];
    float* lvb0 = sm;                           // 64*132
    float* lvb1 = lvb0 + 64 * PAD;
    float* nvb0 = lvb1 + 64 * PAD;
    float* nvb1 = nvb0 + 64 * PAD;
    float* csh  = nvb1 + 64 * PAD;              // 64
    float* gwns = csh + 64;                     // 128
    float* gwls = gwns + D_DIM;                 // 128

    int t = threadIdx.x;
    int warp = t >> 5, lane = t & 31;
    int wm = warp >> 2, wn = warp & 3;          // 2 x 4
    int lp = lane >> 2;                          // 0..7
    int lq = lane & 3;                           // 0..3

    if (t < D_DIM) { gwns[t] = gwn[t]; gwls[t] = gwl[t]; }

    // ---- B fragments (loop-invariant): b = tf32(Wl[k][n])
    // b0 = Wl[(ks*8+lq)*128 + n], b1 = Wl[(ks*8+lq+4)*128 + n], n = wn*32+ns*8+lp
    unsigned Bf[16][4][2];
    {
        int ncol = wn * 32 + lp;
        #pragma unroll
        for (int ks = 0; ks < 16; ks++)
            #pragma unroll
            for (int ns = 0; ns < 4; ns++) {
                Bf[ks][ns][0] = f2tf32(__ldg(&Wl[(ks * 8 + lq) * D_DIM + ncol + ns * 8]));
                Bf[ks][ns][1] = f2tf32(__ldg(&Wl[(ks * 8 + lq + 4) * D_DIM + ncol + ns * 8]));
            }
    }

    float* lvbuf[2] = {lvb0, lvb1};
    float* nvbuf[2] = {nvb0, nvb1};

    // prologue: first tile -> buffer 0
    {
        int p0 = blockIdx.x;
        if (p0 < N_NODES / 2) {
            #pragma unroll
            for (int j = 0; j < 8; j++) {
                int idx = t + j * 256;
                int row = idx >> 5, c4 = idx & 31;
                size_t gb = (((size_t)p0 * 64 + row) << 7) + c4 * 4;
                cp16(lvb0 + row * PAD + c4 * 4, link + gb);
                cp16(nvb0 + row * PAD + c4 * 4, neigh + gb);
            }
        }
        cp_commit();
    }

    int buf = 0;
    for (int p = blockIdx.x; p < N_NODES / 2; p += gridDim.x) {
        // ---- early prefetch of per-node scalars (cover LDG latency)
        float2 ts_pre[4];
        if (lane < 4) {
            int node = p * 2 + wm;
            #pragma unroll
            for (int ns = 0; ns < 4; ns++)
                ts_pre[ns] = *(const float2*)&g_tsf[(size_t)node * D_DIM +
                                                    wn * 32 + ns * 8 + lane * 2];
        }
        int kk = t >> 2, sub = t & 3;
        float pr_pre = 0.0f, tslf_pre = 0.0f;
        if (sub == 0) {
            pr_pre = __ldg(&probs[(size_t)p * 64 + kk]);
            tslf_pre = g_tself[p * 2 + (kk >> 5)];
        }

        cp_wait0();
        __syncthreads();                          // tile ready; prev reads done

        // ---- kick next tile into other buffer
        int pn = p + gridDim.x;
        if (pn < N_NODES / 2) {
            float* ld = lvbuf[buf ^ 1];
            float* nd_ = nvbuf[buf ^ 1];
            #pragma unroll
            for (int j = 0; j < 8; j++) {
                int idx = t + j * 256;
                int row = idx >> 5, c4 = idx & 31;
                size_t gb = (((size_t)pn * 64 + row) << 7) + c4 * 4;
                cp16(ld + row * PAD + c4 * 4, link + gb);
                cp16(nd_ + row * PAD + c4 * 4, neigh + gb);
            }
        }
        cp_commit();

        const float* lvs = lvbuf[buf];
        const float* nvs = nvbuf[buf];

        // ---- gate coefficients c[kk] = sigmoid(tself + nv.gwn + lv.gwl)/(prob*K)
        {
            const float* lrow = lvs + kk * PAD + sub * 32;
            const float* nrow = nvs + kk * PAD + sub * 32;
            const float* gl = gwls + sub * 32;
            const float* gn = gwns + sub * 32;
            float s = 0.0f;
            #pragma unroll 8
            for (int i = 0; i < 32; i++) {
                s = fmaf(lrow[i], gl[i], s);
                s = fmaf(nrow[i], gn[i], s);
            }
            s += __shfl_down_sync(0xffffffffu, s, 1);
            s += __shfl_down_sync(0xffffffffu, s, 2);
            if (sub == 0) {
                float g = sigmoid_tanh(tslf_pre + s);
                csh[kk] = __fdividef(g, pr_pre) * (1.0f / (float)K_NB);
            }
        }
        __syncthreads();                          // csh visible

        // ---- tensor-core GEMM: rows wm*32..+32, cols wn*32..+32, K=128
        float acc0[4][4], acc1[4][4];
        #pragma unroll
        for (int ns = 0; ns < 4; ns++) {
            acc0[ns][0] = acc0[ns][1] = acc0[ns][2] = acc0[ns][3] = 0.0f;
            acc1[ns][0] = acc1[ns][1] = acc1[ns][2] = acc1[ns][3] = 0.0f;
        }

        int rbase = wm * 32 + lp;
        const unsigned* ar0 = (const unsigned*)(lvs + rbase * PAD);          // row lp
        const unsigned* ar1 = (const unsigned*)(lvs + (rbase + 8) * PAD);    // +8
        const unsigned* ar2 = (const unsigned*)(lvs + (rbase + 16) * PAD);   // +16
        const unsigned* ar3 = (const unsigned*)(lvs + (rbase + 24) * PAD);   // +24

        #pragma unroll
        for (int ks = 0; ks < 16; ks++) {
            int d0 = ks * 8 + lq;
            // raw fp32 bits as tf32 (HW truncates mantissa)
            unsigned a00 = ar0[d0], a01 = ar1[d0], a02 = ar0[d0 + 4], a03 = ar1[d0 + 4];
            unsigned a10 = ar2[d0], a11 = ar3[d0], a12 = ar2[d0 + 4], a13 = ar3[d0 + 4];
            #pragma unroll
            for (int ns = 0; ns < 4; ns++) {
                mma_tf32(acc0[ns][0], acc0[ns][1], acc0[ns][2], acc0[ns][3],
                         a00, a01, a02, a03, Bf[ks][ns][0], Bf[ks][ns][1]);
                mma_tf32(acc1[ns][0], acc1[ns][1], acc1[ns][2], acc1[ns][3],
                         a10, a11, a12, a13, Bf[ks][ns][0], Bf[ks][ns][1]);
            }
        }

        // ---- epilogue: sum over this warp's 32 rows (= one node)
        float cA = csh[rbase];
        float cB = csh[rbase + 8];
        float cC = csh[rbase + 16];
        float cD = csh[rbase + 24];

        float ps[8];
        #pragma unroll
        for (int ns = 0; ns < 4; ns++) {
            int e0 = wn * 32 + ns * 8 + lq * 2;
            float2 nv0 = *(const float2*)&nvs[rbase * PAD + e0];
            float2 nv1 = *(const float2*)&nvs[(rbase + 8) * PAD + e0];
            float2 nv2 = *(const float2*)&nvs[(rbase + 16) * PAD + e0];
            float2 nv3 = *(const float2*)&nvs[(rbase + 24) * PAD + e0];
            ps[ns * 2 + 0] = sigmoid_tanh(acc0[ns][0]) * nv0.x * cA +
                             sigmoid_tanh(acc0[ns][2]) * nv1.x * cB +
                             sigmoid_tanh(acc1[ns][0]) * nv2.x * cC +
                             sigmoid_tanh(acc1[ns][2]) * nv3.x * cD;
            ps[ns * 2 + 1] = sigmoid_tanh(acc0[ns][1]) * nv0.y * cA +
                             sigmoid_tanh(acc0[ns][3]) * nv1.y * cB +
                             sigmoid_tanh(acc1[ns][1]) * nv2.y * cC +
                             sigmoid_tanh(acc1[ns][3]) * nv3.y * cD;
        }
        // reduce over lp (8 lanes with same lq)
        #pragma unroll
        for (int o = 4; o <= 16; o <<= 1) {
            #pragma unroll
            for (int i = 0; i < 8; i++)
                ps[i] += __shfl_xor_sync(0xffffffffu, ps[i], o);
        }
        if (lane < 4) {
            int node = p * 2 + wm;
            float* op = out + (size_t)node * D_DIM + wn * 32 + lane * 2;
            #pragma unroll
            for (int ns = 0; ns < 4; ns++) {
                float2 r;
                r.x = fmaxf(ts_pre[ns].x * ps[ns * 2 + 0], 0.0f);
                r.y = fmaxf(ts_pre[ns].y * ps[ns * 2 + 1], 0.0f);
                *(float2*)&op[ns * 8] = r;
            }
        }

        buf ^= 1;
    }
}

// ---------------- launch ----------------------------------------------------
extern "C" void kernel_launch(void* const* d_in, const int* in_sizes, int n_in,
                              void* d_out, int out_size) {
    const float* self_feats = (const float*)d_in[0];
    const float* self_vecs  = (const float*)d_in[1];
    const float* neigh      = (const float*)d_in[2];
    const float* link       = (const float*)d_in[3];
    const float* probs      = (const float*)d_in[4];
    const float* gws        = (const float*)d_in[5];
    const float* gwn        = (const float*)d_in[6];
    const float* gwl        = (const float*)d_in[7];
    const float* Ws         = (const float*)d_in[8];
    const float* Wl         = (const float*)d_in[9];
    float* out = (float*)d_out;

    const int smem_tsf  = (D_DIM * D_DIM + TSF_NODES * D_DIM) * sizeof(float); // 72 KB
    const int smem_main = (4 * 64 * PAD + 64 + 2 * D_DIM) * sizeof(float);     // ~136 KB

    cudaFuncSetAttribute(k_tsf,  cudaFuncAttributeMaxDynamicSharedMemorySize, smem_tsf);
    cudaFuncSetAttribute(k_main, cudaFuncAttributeMaxDynamicSharedMemorySize, smem_main);

    k_tself<<<(N_NODES * 32 + 255) / 256, 256>>>(self_vecs, gws);
    k_tsf<<<N_NODES / TSF_NODES, 256, smem_tsf>>>(self_feats, Ws);
    k_main<<<148, 256, smem_main>>>(neigh, link, probs, gwn, gwl, Wl, out);
}